// round 8
// baseline (speedup 1.0000x reference)
#include <cuda_runtime.h>
#include <cuda_fp16.h>
#include <cstdint>

#define BATCH   16384
#define NF      768
#define FT      1024
#define NROWS   (2*BATCH)      // virtual rows: [0,16384)=stm, [16384,32768)=nstm
#define NPAIRS  (NROWS/2)
#define MAXI    128            // max stored nonzeros per row (mean 32)
#define NSL     8              // output slices
#define OSL     128            // outputs per slice
#define RB      18             // blocks per slice: 8*18 = 144 blocks = 1 wave
#define THREADS 1024           // 32 warps
#define WARPS   32
#define STRIDE  (RB * WARPS)   // 576 pairs per slice-pass
#define NSLOT   16             // 8 slices x 2 perspectives
#define SMEM_W  ((NF + 1) * OSL * 2)            // 196,864 B fp16 W slice (+ zero dummy row)
#define SMEM_BYTES (SMEM_W + 256*4 + 128*4)     // + wc[2][128] + bc[128]

// ---- scratch (device globals; no allocation) ----
__device__ uint16_t g_idx[(size_t)NROWS * MAXI];   // 8 MB indices (dummy-filled to >=48)
__device__ int      g_cnt[NROWS];                  // padded (x4) counts
__device__ float    g_acc[NSLOT * BATCH];          // 1 MB deterministic partials

// ============================================================================
// Kernel 1: warp-per-row scan — COALESCED loads + lane-local mask.
// Lane l, iter j loads row4[l + 32j]; bit b=4j+c maps feature 4l+128j+c.
// Emits compacted indices; fills [cnt, max(48, cnt_pad4)) with dummy NF
// (zero smem row in accum) so paired-row execution is always safe.
// ============================================================================
__global__ __launch_bounds__(256) void scan_kernel(const float* __restrict__ stm,
                                                   const float* __restrict__ nstm) {
    int gtid = blockIdx.x * 256 + threadIdx.x;
    int warp = gtid >> 5;
    int lane = gtid & 31;
    if (warp >= NROWS) return;

    const float* row = (warp < BATCH) ? (stm + (size_t)warp * NF)
                                      : (nstm + (size_t)(warp - BATCH) * NF);
    const float4* row4 = (const float4*)row;
    uint16_t* out = g_idx + (size_t)warp * MAXI;

    unsigned mask = 0;
    #pragma unroll
    for (int j = 0; j < 6; j++) {                    // coalesced: 32 lanes x 16B
        float4 v = row4[lane + 32 * j];
        if (v.x != 0.0f) mask |= 1u << (4 * j + 0);
        if (v.y != 0.0f) mask |= 1u << (4 * j + 1);
        if (v.z != 0.0f) mask |= 1u << (4 * j + 2);
        if (v.w != 0.0f) mask |= 1u << (4 * j + 3);
    }
    int cl = __popc(mask);

    int pre = cl;                                    // warp inclusive scan
    #pragma unroll
    for (int off = 1; off < 32; off <<= 1) {
        int n = __shfl_up_sync(0xffffffffu, pre, off);
        if (lane >= off) pre += n;
    }
    int excl  = pre - cl;
    int total = __shfl_sync(0xffffffffu, pre, 31);

    int basep = excl;
    while (mask) {
        int b = __ffs(mask) - 1;
        mask &= mask - 1;
        if (basep < MAXI)
            out[basep] = (uint16_t)((lane << 2) + ((b >> 2) << 7) + (b & 3));
        basep++;
    }

    int cnt = (total < MAXI) ? total : MAXI;
    int pc = (cnt + 3) & ~3;
    if (pc > MAXI) pc = MAXI;
    int padTo = (pc < 48) ? 48 : pc;
    for (int k = cnt + lane; k < padTo; k += 32)
        out[k] = (uint16_t)NF;                       // dummy -> zero row
    if (lane == 0) g_cnt[warp] = pc;
}

// ============================================================================
// Kernel 2: TWO ROWS PER WARP via LDS.128. Half-warp h (lanes 16h..16h+15)
// serves row 2P+h; lane covers 8 outputs (16B) -> one LDS.128 + 4 HADD2 per
// feature serves both rows' gathers with one address chain each.
// Index prefetch per-lane (half-warp broadcast), groups run to the pair-max
// count (shorter row reads dummies -> zero adds). Fused SCReLU/W_out epilogue
// with half-warp reduction; deterministic slot writes.
// ============================================================================
__global__ __launch_bounds__(THREADS, 1) void accum_kernel(const float* __restrict__ W_ft,
                                                           const float* __restrict__ b_ft,
                                                           const float* __restrict__ W_out) {
    extern __shared__ __half W_sm[];   // [(NF+1)][OSL] | wc[2][128] | bc[128]

    const int s  = blockIdx.x / RB;
    const int rg = blockIdx.x % RB;
    const int obase = s * OSL;
    float* wc = (float*)((char*)W_sm + SMEM_W);
    float* bc = wc + 256;

    // ---- load W slice, convert to fp16, transpose into smem ----
    for (int p = threadIdx.x; p < 64 * (NF / 4); p += THREADS) {
        int fq = p >> 6;                 // 0..191
        int op = (p & 63) << 1;          // even output 0..126
        float4 a = *(const float4*)(W_ft + (size_t)(obase + op)     * NF + 4 * fq);
        float4 b = *(const float4*)(W_ft + (size_t)(obase + op + 1) * NF + 4 * fq);
        __half2* dst = (__half2*)W_sm;
        int w0 = (4 * fq) * (OSL / 2) + (op >> 1);
        dst[w0            ] = __floats2half2_rn(a.x, b.x);
        dst[w0 + OSL / 2  ] = __floats2half2_rn(a.y, b.y);
        dst[w0 + OSL      ] = __floats2half2_rn(a.z, b.z);
        dst[w0 + 3*OSL / 2] = __floats2half2_rn(a.w, b.w);
    }
    if (threadIdx.x < OSL / 2)           // zero dummy row NF
        ((__half2*)W_sm)[NF * (OSL / 2) + threadIdx.x] = __floats2half2_rn(0.f, 0.f);
    if (threadIdx.x < 256)               // W_out table: [persp][out in slice]
        wc[threadIdx.x] = W_out[(threadIdx.x >> 7) * FT + obase + (threadIdx.x & 127)];
    if (threadIdx.x < 128)               // bias table
        bc[threadIdx.x] = b_ft[obase + threadIdx.x];
    __syncthreads();

    const int w    = threadIdx.x >> 5;
    const int lane = threadIdx.x & 31;
    const int half = lane >> 4;
    const int l16  = lane & 15;
    const char* Wl = (const char*)W_sm + l16 * 16;   // lane gather base (bytes)

    for (int P = rg * WARPS + w; P < NPAIRS; P += STRIDE) {
        const int Rh = 2 * P + half;                 // this half-warp's row
        const int cnt = g_cnt[Rh];                   // padded x4
        const uint4* ip4 = (const uint4*)(g_idx + (size_t)Rh * MAXI);

        uint4 u0 = ip4[0], u1 = ip4[1], u2 = ip4[2],
              u3 = ip4[3], u4 = ip4[4], u5 = ip4[5];
        const int cmax = max(cnt, __shfl_xor_sync(0xffffffffu, cnt, 16));
        const int ng = cmax >> 2;

        __half2 z = __floats2half2_rn(0.f, 0.f);
        __half2 a0 = z, a1 = z, a2 = z, a3 = z;      // chain A (outs 0..7 of lane)
        __half2 b0 = z, b1 = z, b2 = z, b3 = z;      // chain B (same outs)

        #define GA(IDX) { uint4 v = *(const uint4*)(Wl + (int)(IDX) * 256); \
            a0 = __hadd2(a0, *(__half2*)&v.x); a1 = __hadd2(a1, *(__half2*)&v.y); \
            a2 = __hadd2(a2, *(__half2*)&v.z); a3 = __hadd2(a3, *(__half2*)&v.w); }
        #define GB(IDX) { uint4 v = *(const uint4*)(Wl + (int)(IDX) * 256); \
            b0 = __hadd2(b0, *(__half2*)&v.x); b1 = __hadd2(b1, *(__half2*)&v.y); \
            b2 = __hadd2(b2, *(__half2*)&v.z); b3 = __hadd2(b3, *(__half2*)&v.w); }
        #define GRP4(LO, HI) { \
            GA(LO & 0xffffu)  GB(LO >> 16)  GA(HI & 0xffffu)  GB(HI >> 16) }

        if (ng >  0) GRP4(u0.x, u0.y)
        if (ng >  1) GRP4(u0.z, u0.w)
        if (ng >  2) GRP4(u1.x, u1.y)
        if (ng >  3) GRP4(u1.z, u1.w)
        if (ng >  4) GRP4(u2.x, u2.y)
        if (ng >  5) GRP4(u2.z, u2.w)
        if (ng >  6) GRP4(u3.x, u3.y)
        if (ng >  7) GRP4(u3.z, u3.w)
        if (ng >  8) GRP4(u4.x, u4.y)
        if (ng >  9) GRP4(u4.z, u4.w)
        if (ng > 10) GRP4(u5.x, u5.y)
        if (ng > 11) GRP4(u5.z, u5.w)
        if (cmax > 48) {                              // rare tail, per-half predicated
            const uint16_t* ip = (const uint16_t*)ip4;
            for (int k = 48; k < cmax; k++) {
                int idx = (k < cnt) ? (int)ip[k] : NF;
                GA(idx)
            }
        }
        #undef GRP4
        #undef GA
        #undef GB

        // ---- epilogue: 8 outputs per lane ----
        const int pr = (P >= NPAIRS / 2);             // pair-uniform perspective
        const float4 bca = *(const float4*)(bc + l16 * 8);
        const float4 bcb = *(const float4*)(bc + l16 * 8 + 4);
        const float4 woa = *(const float4*)(wc + pr * 128 + l16 * 8);
        const float4 wob = *(const float4*)(wc + pr * 128 + l16 * 8 + 4);

        float2 s0 = __half22float2(a0), t0 = __half22float2(b0);
        float2 s1 = __half22float2(a1), t1 = __half22float2(b1);
        float2 s2 = __half22float2(a2), t2 = __half22float2(b2);
        float2 s3 = __half22float2(a3), t3 = __half22float2(b3);
        float p0 = fminf(fmaxf(bca.x + s0.x + t0.x, 0.f), 1.f);
        float p1 = fminf(fmaxf(bca.y + s0.y + t0.y, 0.f), 1.f);
        float p2 = fminf(fmaxf(bca.z + s1.x + t1.x, 0.f), 1.f);
        float p3 = fminf(fmaxf(bca.w + s1.y + t1.y, 0.f), 1.f);
        float p4 = fminf(fmaxf(bcb.x + s2.x + t2.x, 0.f), 1.f);
        float p5 = fminf(fmaxf(bcb.y + s2.y + t2.y, 0.f), 1.f);
        float p6 = fminf(fmaxf(bcb.z + s3.x + t3.x, 0.f), 1.f);
        float p7 = fminf(fmaxf(bcb.w + s3.y + t3.y, 0.f), 1.f);
        float contrib = p0*p0*woa.x + p1*p1*woa.y + p2*p2*woa.z + p3*p3*woa.w
                      + p4*p4*wob.x + p5*p5*wob.y + p6*p6*wob.z + p7*p7*wob.w;

        #pragma unroll
        for (int off = 8; off; off >>= 1)             // reduce within half-warp
            contrib += __shfl_xor_sync(0xffffffffu, contrib, off);

        if (l16 == 0)
            g_acc[(size_t)(s * 2 + pr) * BATCH + (Rh & (BATCH - 1))] = contrib;
    }
}

// ============================================================================
// Kernel 3: sum 16 deterministic partials, add b_out, sigmoid.
// ============================================================================
__global__ __launch_bounds__(256) void finalize_kernel(const float* __restrict__ b_out,
                                                       float* __restrict__ out) {
    int b = blockIdx.x * 256 + threadIdx.x;
    if (b >= BATCH) return;
    float x = b_out[0];
    #pragma unroll
    for (int sl = 0; sl < NSLOT; sl++)
        x += g_acc[(size_t)sl * BATCH + b];
    out[b] = 1.0f / (1.0f + expf(-x));
}

extern "C" void kernel_launch(void* const* d_in, const int* in_sizes, int n_in,
                              void* d_out, int out_size) {
    const float* stm   = (const float*)d_in[0];
    const float* nstm  = (const float*)d_in[1];
    const float* W_ft  = (const float*)d_in[2];
    const float* b_ft  = (const float*)d_in[3];
    const float* W_out = (const float*)d_in[4];
    const float* b_out = (const float*)d_in[5];
    float* out = (float*)d_out;

    cudaFuncSetAttribute(accum_kernel,
                         cudaFuncAttributeMaxDynamicSharedMemorySize, SMEM_BYTES);

    scan_kernel<<<NROWS / 8, 256>>>(stm, nstm);                            // 4096 blocks
    accum_kernel<<<NSL * RB, THREADS, SMEM_BYTES>>>(W_ft, b_ft, W_out);    // 144 blocks
    finalize_kernel<<<(BATCH + 255) / 256, 256>>>(b_out, out);
}